// round 2
// baseline (speedup 1.0000x reference)
#include <cuda_runtime.h>

#define NN   8192
#define INF  512
#define OUTF 256
#define MAXNB 1024

// Scratch (allocation-free rule: __device__ globals)
__device__ float g_h[NN * OUTF];     // X @ W
__device__ float g_hgc[NN * OUTF];   // X @ W_gc
__device__ float g_fs[NN];           // h @ a[:F]
__device__ float g_fd[NN];           // h @ a[F:]

// ---------------------------------------------------------------------------
// GEMM: computes both h = X@W and hgc = X@W_gc as one [8192 x 512] output,
// columns 0..255 -> g_h, 256..511 -> g_hgc. 128x128 tile, 8x8 per thread.
// ---------------------------------------------------------------------------
__global__ __launch_bounds__(256) void gemm_kernel(const float* __restrict__ X,
                                                   const float* __restrict__ W,
                                                   const float* __restrict__ Wgc) {
    const int BM = 128, BK = 16;
    __shared__ float As[BK * 129];   // transposed A tile, padded stride
    __shared__ float Bs[BK * 128];

    int bm = blockIdx.x, bn = blockIdx.y;            // bn in 0..3
    const float* Bbase = (bn < 2) ? W : Wgc;         // both [512 x 256] row-major
    int c0 = (bn & 1) * 128;                         // column offset within 256
    int m0 = bm * BM;
    int tid = threadIdx.x;
    int tr = tid >> 4, tc = tid & 15;                // 16x16 thread grid

    float acc[8][8];
    #pragma unroll
    for (int i = 0; i < 8; i++)
        #pragma unroll
        for (int j = 0; j < 8; j++) acc[i][j] = 0.f;

    for (int k0 = 0; k0 < INF; k0 += BK) {
        // A tile: 128 rows x 16 k (transposed into As[k][m])
        #pragma unroll
        for (int r = 0; r < 2; r++) {
            int f4 = tid + 256 * r;
            int row = f4 >> 2;
            int kk = (f4 & 3) * 4;
            float4 v = *(const float4*)(X + (size_t)(m0 + row) * INF + k0 + kk);
            As[(kk + 0) * 129 + row] = v.x;
            As[(kk + 1) * 129 + row] = v.y;
            As[(kk + 2) * 129 + row] = v.z;
            As[(kk + 3) * 129 + row] = v.w;
        }
        // B tile: 16 k x 128 cols
        #pragma unroll
        for (int r = 0; r < 2; r++) {
            int f4 = tid + 256 * r;
            int krow = f4 >> 5;
            int cc = (f4 & 31) * 4;
            *(float4*)(Bs + krow * 128 + cc) =
                *(const float4*)(Bbase + (size_t)(k0 + krow) * OUTF + c0 + cc);
        }
        __syncthreads();

        #pragma unroll
        for (int k = 0; k < BK; k++) {
            float av[8], bv[8];
            #pragma unroll
            for (int i = 0; i < 8; i++) av[i] = As[k * 129 + tr * 8 + i];
            #pragma unroll
            for (int j = 0; j < 8; j++) bv[j] = Bs[k * 128 + tc * 8 + j];
            #pragma unroll
            for (int i = 0; i < 8; i++)
                #pragma unroll
                for (int j = 0; j < 8; j++)
                    acc[i][j] += av[i] * bv[j];
        }
        __syncthreads();
    }

    float* outp = (bn < 2) ? g_h : g_hgc;
    #pragma unroll
    for (int i = 0; i < 8; i++) {
        int row = m0 + tr * 8 + i;
        #pragma unroll
        for (int j = 0; j < 8; j += 4) {
            float4 v = make_float4(acc[i][j], acc[i][j + 1], acc[i][j + 2], acc[i][j + 3]);
            *(float4*)(outp + (size_t)row * OUTF + c0 + tc * 8 + j) = v;
        }
    }
}

// ---------------------------------------------------------------------------
// f_src / f_dst: one warp per row, dot of h_row with a[:256] and a[256:]
// ---------------------------------------------------------------------------
__global__ __launch_bounds__(256) void f_kernel(const float* __restrict__ a) {
    int warp = (blockIdx.x * blockDim.x + threadIdx.x) >> 5;
    int lane = threadIdx.x & 31;
    if (warp >= NN) return;
    const float* hrow = g_h + (size_t)warp * OUTF;
    float s1 = 0.f, s2 = 0.f;
    #pragma unroll
    for (int c = lane; c < OUTF; c += 32) {
        float hv = hrow[c];
        s1 += hv * a[c];
        s2 += hv * a[OUTF + c];
    }
    #pragma unroll
    for (int o = 16; o; o >>= 1) {
        s1 += __shfl_xor_sync(0xFFFFFFFFu, s1, o);
        s2 += __shfl_xor_sync(0xFFFFFFFFu, s2, o);
    }
    if (lane == 0) { g_fs[warp] = s1; g_fd[warp] = s2; }
}

// ---------------------------------------------------------------------------
// Fused masked-softmax attention + graph-conv accumulation.
// One block per row. Exploits sparsity: masked entries contribute exactly 0.
// out_i = sum_{j: adj=1} ( softmax_w(i,j) * h_j + hgc_j ) + b_gc
// ---------------------------------------------------------------------------
__global__ __launch_bounds__(256) void att_kernel(const float* __restrict__ adj,
                                                  const float* __restrict__ bgc,
                                                  float* __restrict__ out) {
    __shared__ int   s_idx[MAXNB];
    __shared__ float s_e[MAXNB];
    __shared__ int   s_cnt;
    __shared__ float s_red[256];

    int row = blockIdx.x;
    int tid = threadIdx.x;
    if (tid == 0) s_cnt = 0;
    __syncthreads();

    // Phase A: scan adjacency row, compact neighbors + leaky-relu logits
    float fsi = g_fs[row];
    const float* arow = adj + (size_t)row * NN;
    for (int j = tid; j < NN; j += 256) {
        if (arow[j] > 0.f) {
            float e = fsi + g_fd[j];
            e = (e > 0.f) ? e : 0.2f * e;
            int p = atomicAdd(&s_cnt, 1);
            if (p < MAXNB) { s_idx[p] = j; s_e[p] = e; }
        }
    }
    __syncthreads();
    int cnt = min(s_cnt, MAXNB);

    float acc = bgc[tid];

    if (cnt > 0) {
        // max reduction
        float lm = -3e38f;
        for (int k = tid; k < cnt; k += 256) lm = fmaxf(lm, s_e[k]);
        s_red[tid] = lm;
        __syncthreads();
        #pragma unroll
        for (int o = 128; o; o >>= 1) {
            if (tid < o) s_red[tid] = fmaxf(s_red[tid], s_red[tid + o]);
            __syncthreads();
        }
        float mx = s_red[0];
        __syncthreads();

        // sum of exp
        float ls = 0.f;
        for (int k = tid; k < cnt; k += 256) ls += expf(s_e[k] - mx);
        s_red[tid] = ls;
        __syncthreads();
        #pragma unroll
        for (int o = 128; o; o >>= 1) {
            if (tid < o) s_red[tid] += s_red[tid + o];
            __syncthreads();
        }
        float inv = 1.0f / s_red[0];
        __syncthreads();

        // normalize in place
        for (int k = tid; k < cnt; k += 256) s_e[k] = expf(s_e[k] - mx) * inv;
        __syncthreads();

        // Phase B: gather-accumulate. Thread tid owns output column tid.
        #pragma unroll 4
        for (int k = 0; k < cnt; k++) {
            int j = s_idx[k];
            float w = s_e[k];
            acc += w * g_h[(size_t)j * OUTF + tid] + g_hgc[(size_t)j * OUTF + tid];
        }
    } else {
        // all-masked row: reference softmax becomes uniform 1/N over ALL columns,
        // and the gc branch contributes only the bias.
        const float wu = 1.0f / (float)NN;
        for (int j = 0; j < NN; j++) acc += wu * g_h[(size_t)j * OUTF + tid];
    }

    out[(size_t)row * OUTF + tid] = acc;
}

// ---------------------------------------------------------------------------
extern "C" void kernel_launch(void* const* d_in, const int* in_sizes, int n_in,
                              void* d_out, int out_size) {
    const float* X   = (const float*)d_in[0];  // [8192, 512]
    const float* adj = (const float*)d_in[1];  // [8192, 8192]
    const float* W   = (const float*)d_in[2];  // [512, 256]
    const float* a   = (const float*)d_in[3];  // [512, 1]
    const float* Wgc = (const float*)d_in[4];  // [512, 256]
    const float* bgc = (const float*)d_in[5];  // [256]
    float* out = (float*)d_out;                // [8192, 256]

    gemm_kernel<<<dim3(64, 4), 256>>>(X, W, Wgc);
    f_kernel<<<NN / 8, 256>>>(a);
    att_kernel<<<NN, 256>>>(adj, bgc, out);
}

// round 3
// speedup vs baseline: 1.0340x; 1.0340x over previous
#include <cuda_runtime.h>
#include <cuda_fp16.h>

#define NN   8192
#define INF  512
#define OUTF 256
#define MAXNB 1024

// ---------------- scratch (__device__ globals: allocation-free rule) --------
__device__ float  g_fsp[2][NN];          // f_src partials (col-half 0/1)
__device__ float  g_fdp[2][NN];          // f_dst partials
__device__ __half g_pack[NN * OUTF * 2]; // interleaved {h, hgc} per (row,col)
__device__ int    g_ncnt[NN];            // neighbor count per row
__device__ int    g_nidx[NN * MAXNB];    // neighbor indices per row

// ---------------- packed fp32x2 helpers ------------------------------------
#define FMA2(d, a, b) \
    asm("fma.rn.f32x2 %0, %1, %2, %0;" : "+l"(d) : "l"(a), "l"(b))
#define PACKDUP(d, s) \
    asm("mov.b64 %0, {%1, %1};" : "=l"(d) : "r"(__float_as_uint(s)))
#define UNPACK2(lo, hi, d) \
    asm("mov.b64 {%0, %1}, %2;" : "=r"(lo), "=r"(hi) : "l"(d))

// ---------------------------------------------------------------------------
// Kernel A (heterogeneous):
//   blocks [0,256): FFMA2 GEMM -> h (bn 0,1) / hgc (bn 2,3), fp16 packed out,
//                   + f_src/f_dst per-block partials in the epilogue.
//   blocks [256, 256+NN): adjacency-row scan -> compacted neighbor lists.
// The scan is DRAM-bound, the GEMM fma-bound: they overlap on-chip.
// ---------------------------------------------------------------------------
__global__ __launch_bounds__(256) void kernelA(const float* __restrict__ X,
                                               const float* __restrict__ W,
                                               const float* __restrict__ Wgc,
                                               const float* __restrict__ avec,
                                               const float* __restrict__ adj) {
    __shared__ float As[2][16 * 132];   // [k][m], padded stride (16B aligned rows)
    __shared__ float Bs[2][16 * 128];   // [k][n]
    __shared__ int   s_cnt;

    const int bid = blockIdx.x;
    const int tid = threadIdx.x;

    if (bid >= 256) {
        // ---------------- adjacency scan ----------------
        int row = bid - 256;
        if (tid == 0) s_cnt = 0;
        __syncthreads();
        const float4* arow = (const float4*)(adj + (size_t)row * NN);
        #pragma unroll
        for (int r = 0; r < 8; r++) {
            int q = tid + 256 * r;
            float4 v = arow[q];
            int j0 = q * 4;
            if (v.x > 0.f) { int p = atomicAdd(&s_cnt, 1); if (p < MAXNB) g_nidx[row * MAXNB + p] = j0; }
            if (v.y > 0.f) { int p = atomicAdd(&s_cnt, 1); if (p < MAXNB) g_nidx[row * MAXNB + p] = j0 + 1; }
            if (v.z > 0.f) { int p = atomicAdd(&s_cnt, 1); if (p < MAXNB) g_nidx[row * MAXNB + p] = j0 + 2; }
            if (v.w > 0.f) { int p = atomicAdd(&s_cnt, 1); if (p < MAXNB) g_nidx[row * MAXNB + p] = j0 + 3; }
        }
        __syncthreads();
        if (tid == 0) g_ncnt[row] = min(s_cnt, MAXNB);
        return;
    }

    // ---------------- GEMM ----------------
    const int bm = bid & 63, bn = bid >> 6;
    const float* Bp = (bn < 2) ? W : Wgc;
    const int c0 = (bn & 1) * 128;
    const int m0 = bm * 128;
    const int tr = tid >> 4, tc = tid & 15;

    // loader geometry
    const int arow_l = tid >> 2;           // 0..63
    const int akk    = (tid & 3) * 4;      // 0,4,8,12
    const int bkr    = tid >> 5;           // 0..7
    const int bcc    = (tid & 31) * 4;     // 0..124

    unsigned long long acc2[8][4];
    #pragma unroll
    for (int i = 0; i < 8; i++)
        #pragma unroll
        for (int p = 0; p < 4; p++) acc2[i][p] = 0ULL;

    float4 a0, a1, b0, b1;
    // preload tile 0
    a0 = *(const float4*)(X + (size_t)(m0 + arow_l) * INF + akk);
    a1 = *(const float4*)(X + (size_t)(m0 + arow_l + 64) * INF + akk);
    b0 = *(const float4*)(Bp + (size_t)bkr * OUTF + c0 + bcc);
    b1 = *(const float4*)(Bp + (size_t)(bkr + 8) * OUTF + c0 + bcc);
    {
        float* pa = As[0];
        pa[(akk + 0) * 132 + arow_l] = a0.x; pa[(akk + 1) * 132 + arow_l] = a0.y;
        pa[(akk + 2) * 132 + arow_l] = a0.z; pa[(akk + 3) * 132 + arow_l] = a0.w;
        pa[(akk + 0) * 132 + arow_l + 64] = a1.x; pa[(akk + 1) * 132 + arow_l + 64] = a1.y;
        pa[(akk + 2) * 132 + arow_l + 64] = a1.z; pa[(akk + 3) * 132 + arow_l + 64] = a1.w;
        *(float4*)(Bs[0] + bkr * 128 + bcc) = b0;
        *(float4*)(Bs[0] + (bkr + 8) * 128 + bcc) = b1;
    }
    __syncthreads();

    int buf = 0;
    for (int k0 = 0; k0 < INF; k0 += 16) {
        const bool last = (k0 + 16 >= INF);
        if (!last) {
            a0 = *(const float4*)(X + (size_t)(m0 + arow_l) * INF + k0 + 16 + akk);
            a1 = *(const float4*)(X + (size_t)(m0 + arow_l + 64) * INF + k0 + 16 + akk);
            b0 = *(const float4*)(Bp + (size_t)(k0 + 16 + bkr) * OUTF + c0 + bcc);
            b1 = *(const float4*)(Bp + (size_t)(k0 + 16 + bkr + 8) * OUTF + c0 + bcc);
        }
        const float* pA = As[buf];
        const float* pB = Bs[buf];
        #pragma unroll
        for (int k = 0; k < 16; k++) {
            float4 x0 = *(const float4*)(pA + k * 132 + tr * 8);
            float4 x1 = *(const float4*)(pA + k * 132 + tr * 8 + 4);
            const unsigned long long* pb64 =
                (const unsigned long long*)(pB + k * 128 + tc * 8);
            unsigned long long b2_0 = pb64[0], b2_1 = pb64[1],
                               b2_2 = pb64[2], b2_3 = pb64[3];
            float av[8] = {x0.x, x0.y, x0.z, x0.w, x1.x, x1.y, x1.z, x1.w};
            unsigned long long ad[8];
            #pragma unroll
            for (int i = 0; i < 8; i++) PACKDUP(ad[i], av[i]);
            #pragma unroll
            for (int i = 0; i < 8; i++) {
                FMA2(acc2[i][0], ad[i], b2_0);
                FMA2(acc2[i][1], ad[i], b2_1);
                FMA2(acc2[i][2], ad[i], b2_2);
                FMA2(acc2[i][3], ad[i], b2_3);
            }
        }
        if (!last) {
            float* pa = As[buf ^ 1];
            pa[(akk + 0) * 132 + arow_l] = a0.x; pa[(akk + 1) * 132 + arow_l] = a0.y;
            pa[(akk + 2) * 132 + arow_l] = a0.z; pa[(akk + 3) * 132 + arow_l] = a0.w;
            pa[(akk + 0) * 132 + arow_l + 64] = a1.x; pa[(akk + 1) * 132 + arow_l + 64] = a1.y;
            pa[(akk + 2) * 132 + arow_l + 64] = a1.z; pa[(akk + 3) * 132 + arow_l + 64] = a1.w;
            *(float4*)(Bs[buf ^ 1] + bkr * 128 + bcc) = b0;
            *(float4*)(Bs[buf ^ 1] + (bkr + 8) * 128 + bcc) = b1;
            __syncthreads();
            buf ^= 1;
        }
    }

    // unpack accumulators
    float accf[8][8];
    #pragma unroll
    for (int i = 0; i < 8; i++)
        #pragma unroll
        for (int p = 0; p < 4; p++) {
            unsigned int lo, hi;
            UNPACK2(lo, hi, acc2[i][p]);
            accf[i][2 * p]     = __uint_as_float(lo);
            accf[i][2 * p + 1] = __uint_as_float(hi);
        }

    // fp16 packed store: h -> even half, hgc -> odd half
    const int half_off = (bn < 2) ? 0 : 1;
    #pragma unroll
    for (int i = 0; i < 8; i++) {
        int row = m0 + tr * 8 + i;
        #pragma unroll
        for (int j = 0; j < 8; j++)
            g_pack[((size_t)row * OUTF + c0 + tc * 8 + j) * 2 + half_off] =
                __float2half(accf[i][j]);
    }

    // f_src / f_dst per-block partials (deterministic: indexed by bn)
    if (bn < 2) {
        float aw1[8], aw2[8];
        #pragma unroll
        for (int j = 0; j < 8; j++) {
            aw1[j] = avec[c0 + tc * 8 + j];
            aw2[j] = avec[OUTF + c0 + tc * 8 + j];
        }
        #pragma unroll
        for (int i = 0; i < 8; i++) {
            float s1 = 0.f, s2 = 0.f;
            #pragma unroll
            for (int j = 0; j < 8; j++) {
                s1 += accf[i][j] * aw1[j];
                s2 += accf[i][j] * aw2[j];
            }
            #pragma unroll
            for (int o = 8; o; o >>= 1) {
                s1 += __shfl_xor_sync(0xFFFFFFFFu, s1, o);
                s2 += __shfl_xor_sync(0xFFFFFFFFu, s2, o);
            }
            if (tc == 0) {
                g_fsp[bn][m0 + tr * 8 + i] = s1;
                g_fdp[bn][m0 + tr * 8 + i] = s2;
            }
        }
    }
}

// ---------------------------------------------------------------------------
// Kernel B: masked softmax + fused gather of (att*h + hgc), fp16 half2 loads.
// ---------------------------------------------------------------------------
__global__ __launch_bounds__(256) void kernelB(const float* __restrict__ bgc,
                                               float* __restrict__ out) {
    __shared__ int   s_idx[MAXNB];
    __shared__ float s_e[MAXNB];
    __shared__ float s_red[256];

    const int row = blockIdx.x;
    const int tid = threadIdx.x;
    const int cnt = g_ncnt[row];

    float outv;
    if (cnt > 0) {
        const float fsi = g_fsp[0][row] + g_fsp[1][row];
        float lm = -3e38f;
        for (int k = tid; k < cnt; k += 256) {
            int j = g_nidx[row * MAXNB + k];
            float e = fsi + g_fdp[0][j] + g_fdp[1][j];
            e = (e > 0.f) ? e : 0.2f * e;
            s_idx[k] = j;
            s_e[k] = e;
            lm = fmaxf(lm, e);
        }
        s_red[tid] = lm;
        __syncthreads();
        #pragma unroll
        for (int o = 128; o; o >>= 1) {
            if (tid < o) s_red[tid] = fmaxf(s_red[tid], s_red[tid + o]);
            __syncthreads();
        }
        const float mx = s_red[0];
        __syncthreads();

        float ls = 0.f;
        for (int k = tid; k < cnt; k += 256) {
            float w = expf(s_e[k] - mx);
            s_e[k] = w;
            ls += w;
        }
        s_red[tid] = ls;
        __syncthreads();
        #pragma unroll
        for (int o = 128; o; o >>= 1) {
            if (tid < o) s_red[tid] += s_red[tid + o];
            __syncthreads();
        }
        const float inv = 1.0f / s_red[0];
        __syncthreads();

        // gather: thread tid owns output column tid
        float acc_att = 0.f, acc_gc = 0.f;
        const __half2* hp = (const __half2*)g_pack;
        #pragma unroll 4
        for (int k = 0; k < cnt; k++) {
            int j = s_idx[k];
            float w = s_e[k];
            float2 f2 = __half22float2(hp[(size_t)j * OUTF + tid]);
            acc_att += w * f2.x;
            acc_gc += f2.y;
        }
        outv = bgc[tid] + inv * acc_att + acc_gc;
    } else {
        // all-masked row: softmax is uniform 1/N over all columns; gc = bias only
        const __half2* hp = (const __half2*)g_pack;
        float acc = 0.f;
        for (int j = 0; j < NN; j++)
            acc += __half2float(hp[(size_t)j * OUTF + tid].x);
        outv = bgc[tid] + acc * (1.0f / (float)NN);
    }
    out[(size_t)row * OUTF + tid] = outv;
}

// ---------------------------------------------------------------------------
extern "C" void kernel_launch(void* const* d_in, const int* in_sizes, int n_in,
                              void* d_out, int out_size) {
    const float* X   = (const float*)d_in[0];  // [8192, 512]
    const float* adj = (const float*)d_in[1];  // [8192, 8192]
    const float* W   = (const float*)d_in[2];  // [512, 256]
    const float* a   = (const float*)d_in[3];  // [512, 1]
    const float* Wgc = (const float*)d_in[4];  // [512, 256]
    const float* bgc = (const float*)d_in[5];  // [256]
    float* out = (float*)d_out;                // [8192, 256]

    kernelA<<<256 + NN, 256>>>(X, W, Wgc, a, adj);
    kernelB<<<NN, 256>>>(bgc, out);
}

// round 6
// speedup vs baseline: 1.2400x; 1.1992x over previous
#include <cuda_runtime.h>
#include <cuda_fp16.h>
#include <cuda_bf16.h>
#include <cstdint>

#define NN    8192
#define INF   512
#define OUTF  256
#define MAXNB 1024

// ---------------- scratch (__device__ globals: allocation-free rule) --------
__device__ float          g_fsp[4][NN];     // f_src partials (bn*2+wn)
__device__ float          g_fdp[4][NN];
__device__ float          g_fs[NN];
__device__ float          g_fd[NN];
__device__ __half         g_pack[NN * 512]; // [row][0..255]=h, [256..511]=hgc
__device__ int            g_ncnt[NN];
__device__ int            g_nidx[NN * MAXNB]; // pre-scaled j*512
__device__ __nv_bfloat16  g_xh[NN * INF];   // bf16 hi of X  [row][512]
__device__ __nv_bfloat16  g_xl[NN * INF];   // bf16 lo of X
__device__ __nv_bfloat16  g_bh[INF * 512];  // [k][512] = W | Wgc (hi)
__device__ __nv_bfloat16  g_bl[INF * 512];  // lo

// ---------------- helpers ---------------------------------------------------
__device__ __forceinline__ uint32_t smem_u32(const void* p) {
    uint32_t a;
    asm("{ .reg .u64 t; cvta.to.shared.u64 t, %1; cvt.u32.u64 %0, t; }"
        : "=r"(a) : "l"(p));
    return a;
}
#define CPASYNC16(dst, src) \
    asm volatile("cp.async.cg.shared.global [%0], [%1], 16;" \
                 :: "r"(dst), "l"(src) : "memory")
#define CPCOMMIT() asm volatile("cp.async.commit_group;" ::: "memory")
#define CPWAIT(n)  asm volatile("cp.async.wait_group %0;" :: "n"(n) : "memory")

__device__ __forceinline__ void ldsm_x4(uint32_t (&r)[4], uint32_t addr) {
    asm volatile("ldmatrix.sync.aligned.m8n8.x4.shared.b16 {%0,%1,%2,%3}, [%4];"
                 : "=r"(r[0]), "=r"(r[1]), "=r"(r[2]), "=r"(r[3]) : "r"(addr));
}
__device__ __forceinline__ void ldsm_x4t(uint32_t (&r)[4], uint32_t addr) {
    asm volatile("ldmatrix.sync.aligned.m8n8.x4.trans.shared.b16 {%0,%1,%2,%3}, [%4];"
                 : "=r"(r[0]), "=r"(r[1]), "=r"(r[2]), "=r"(r[3]) : "r"(addr));
}
__device__ __forceinline__ void mma_bf16(float* c, const uint32_t* a,
                                         uint32_t b0, uint32_t b1) {
    asm volatile("mma.sync.aligned.m16n8k16.row.col.f32.bf16.bf16.f32 "
                 "{%0,%1,%2,%3}, {%4,%5,%6,%7}, {%8,%9}, {%0,%1,%2,%3};"
                 : "+f"(c[0]), "+f"(c[1]), "+f"(c[2]), "+f"(c[3])
                 : "r"(a[0]), "r"(a[1]), "r"(a[2]), "r"(a[3]), "r"(b0), "r"(b1));
}

// ---------------------------------------------------------------------------
// prepX: X fp32 -> (Xh, Xl) bf16 split
// ---------------------------------------------------------------------------
__global__ __launch_bounds__(256) void prepX(const float* __restrict__ X) {
    int i = blockIdx.x * 256 + threadIdx.x;          // float4 index
    float4 v = ((const float4*)X)[i];
    __nv_bfloat16 hv[4], lv[4];
    float f[4] = {v.x, v.y, v.z, v.w};
    #pragma unroll
    for (int j = 0; j < 4; j++) {
        hv[j] = __float2bfloat16_rn(f[j]);
        lv[j] = __float2bfloat16_rn(f[j] - __bfloat162float(hv[j]));
    }
    *(uint2*)(g_xh + (size_t)i * 4) = *(uint2*)hv;
    *(uint2*)(g_xl + (size_t)i * 4) = *(uint2*)lv;
}

// ---------------------------------------------------------------------------
// prepB: W,Wgc [512][256] fp32 -> g_bh/g_bl [512][512] bf16 (no transpose)
// ---------------------------------------------------------------------------
__global__ __launch_bounds__(256) void prepB(const float* __restrict__ W,
                                             const float* __restrict__ Wgc) {
    int k = blockIdx.x, n = threadIdx.x;
    float w = W[k * 256 + n];
    __nv_bfloat16 hb = __float2bfloat16_rn(w);
    g_bh[k * 512 + n] = hb;
    g_bl[k * 512 + n] = __float2bfloat16_rn(w - __bfloat162float(hb));
    float wg = Wgc[k * 256 + n];
    hb = __float2bfloat16_rn(wg);
    g_bh[k * 512 + 256 + n] = hb;
    g_bl[k * 512 + 256 + n] = __float2bfloat16_rn(wg - __bfloat162float(hb));
}

// ---------------------------------------------------------------------------
// kernelG (heterogeneous): blocks [0,256) HMMA GEMM, blocks [256,256+NN) scan
// GEMM: C[8192 x 512] = Xsplit @ Bsplit (3-term bf16), K'=1536, 48 chunks of 32
// smem: A[128][40]e (80B rows) + B[32][136]e (272B rows), double buffered.
// ---------------------------------------------------------------------------
#define ABYTES 10240
#define BUFB   18944
__global__ __launch_bounds__(256) void kernelG(const float* __restrict__ avec,
                                               const float* __restrict__ adj) {
    __shared__ __align__(16) char sm_ab[2 * BUFB];
    __shared__ float s_avec[512];
    __shared__ int s_cnt;

    const int bid = blockIdx.x;
    const int tid = threadIdx.x;

    if (bid >= 256) {
        // -------- adjacency scan --------
        int row = bid - 256;
        if (tid == 0) s_cnt = 0;
        __syncthreads();
        const float4* arow = (const float4*)(adj + (size_t)row * NN);
        #pragma unroll
        for (int r = 0; r < 8; r++) {
            int q = tid + 256 * r;
            float4 v = arow[q];
            int j0 = q * 4;
            if (v.x > 0.f) { int p = atomicAdd(&s_cnt, 1); if (p < MAXNB) g_nidx[row * MAXNB + p] = (j0 + 0) * 512; }
            if (v.y > 0.f) { int p = atomicAdd(&s_cnt, 1); if (p < MAXNB) g_nidx[row * MAXNB + p] = (j0 + 1) * 512; }
            if (v.z > 0.f) { int p = atomicAdd(&s_cnt, 1); if (p < MAXNB) g_nidx[row * MAXNB + p] = (j0 + 2) * 512; }
            if (v.w > 0.f) { int p = atomicAdd(&s_cnt, 1); if (p < MAXNB) g_nidx[row * MAXNB + p] = (j0 + 3) * 512; }
        }
        __syncthreads();
        if (tid == 0) g_ncnt[row] = min(s_cnt, MAXNB);
        return;
    }

    // -------- GEMM block --------
    const int bm = bid & 63, bn = bid >> 6;          // bn: 0,1=h  2,3=hgc
    const int m0 = bm * 128;
    const int wid = tid >> 5, lane = tid & 31;
    const int wm = wid & 3, wn = wid >> 2;           // warp tile 32m x 64n
    const uint32_t smbase = smem_u32(sm_ab);

    s_avec[tid] = avec[tid];
    s_avec[tid + 256] = avec[tid + 256];

    float cacc[2][8][4];
    #pragma unroll
    for (int i = 0; i < 2; i++)
        #pragma unroll
        for (int j = 0; j < 8; j++)
            #pragma unroll
            for (int e = 0; e < 4; e++) cacc[i][j][e] = 0.f;

    auto issue = [&](int c) {
        uint32_t buf = smbase + (uint32_t)(c & 1) * BUFB;
        int seg = c >> 4;
        const uint4* asrc = (const uint4*)((seg < 2) ? g_xh : g_xl);
        const uint4* bsrc = (const uint4*)((seg == 1) ? g_bl : g_bh);
        int kq = (c & 15) * 4;                       // A uint4 col offset
        #pragma unroll
        for (int i = 0; i < 2; i++) {
            int idx = tid + 256 * i;
            int r = idx >> 2, q = idx & 3;
            CPASYNC16(buf + r * 80 + q * 16, asrc + (size_t)(m0 + r) * 64 + kq + q);
        }
        int kr0 = (c & 15) * 32;                     // B k-row base
        #pragma unroll
        for (int i = 0; i < 2; i++) {
            int idx = tid + 256 * i;
            int rr = idx >> 4, q = idx & 15;
            CPASYNC16(buf + ABYTES + rr * 272 + q * 16,
                      bsrc + (size_t)(kr0 + rr) * 64 + bn * 16 + q);
        }
    };

    issue(0); CPCOMMIT();
    for (int c = 0; c < 48; c++) {
        if (c + 1 < 48) { issue(c + 1); CPCOMMIT(); CPWAIT(1); }
        else            { CPWAIT(0); }
        __syncthreads();
        uint32_t Ab = smbase + (uint32_t)(c & 1) * BUFB;
        uint32_t Bb = Ab + ABYTES;
        #pragma unroll
        for (int ks = 0; ks < 2; ks++) {
            int kk = ks * 16;
            uint32_t a[2][4], b[4][4];
            #pragma unroll
            for (int mf = 0; mf < 2; mf++)
                ldsm_x4(a[mf], Ab + (uint32_t)((wm * 32 + mf * 16 + (lane & 15)) * 80
                                               + (kk + (lane >> 4) * 8) * 2));
            #pragma unroll
            for (int ng = 0; ng < 4; ng++)
                ldsm_x4t(b[ng], Bb + (uint32_t)((kk + (lane & 15)) * 272
                                                + (wn * 64 + ng * 16 + (lane >> 4) * 8) * 2));
            #pragma unroll
            for (int mf = 0; mf < 2; mf++)
                #pragma unroll
                for (int nf = 0; nf < 8; nf++)
                    mma_bf16(cacc[mf][nf], a[mf],
                             b[nf >> 1][(nf & 1) * 2], b[nf >> 1][(nf & 1) * 2 + 1]);
        }
        __syncthreads();
    }

    // -------- epilogue: fp16 pack + f partials --------
    const int pidx = bn * 2 + wn;                    // valid when bn < 2
    #pragma unroll
    for (int mf = 0; mf < 2; mf++) {
        #pragma unroll
        for (int half = 0; half < 2; half++) {
            int row = m0 + wm * 32 + mf * 16 + (lane >> 2) + half * 8;
            int colbase = bn * 128 + wn * 64 + 2 * (lane & 3);
            __half2* dst = (__half2*)g_pack + ((size_t)row * 512 + colbase) / 2;
            float s1 = 0.f, s2 = 0.f;
            #pragma unroll
            for (int nf = 0; nf < 8; nf++) {
                float v0 = cacc[mf][nf][half * 2 + 0];
                float v1 = cacc[mf][nf][half * 2 + 1];
                if (bn < 2) {
                    int cc = bn * 128 + wn * 64 + nf * 8 + 2 * (lane & 3);
                    s1 += v0 * s_avec[cc] + v1 * s_avec[cc + 1];
                    s2 += v0 * s_avec[256 + cc] + v1 * s_avec[256 + cc + 1];
                }
                dst[nf * 4] = __floats2half2_rn(v0, v1);
            }
            if (bn < 2) {
                s1 += __shfl_xor_sync(0xFFFFFFFFu, s1, 1);
                s1 += __shfl_xor_sync(0xFFFFFFFFu, s1, 2);
                s2 += __shfl_xor_sync(0xFFFFFFFFu, s2, 1);
                s2 += __shfl_xor_sync(0xFFFFFFFFu, s2, 2);
                if ((lane & 3) == 0) {
                    g_fsp[pidx][row] = s1;
                    g_fdp[pidx][row] = s2;
                }
            }
        }
    }
}

// ---------------------------------------------------------------------------
__global__ __launch_bounds__(256) void kernelR() {
    int i = blockIdx.x * 256 + threadIdx.x;
    g_fs[i] = g_fsp[0][i] + g_fsp[1][i] + g_fsp[2][i] + g_fsp[3][i];
    g_fd[i] = g_fdp[0][i] + g_fdp[1][i] + g_fdp[2][i] + g_fdp[3][i];
}

// ---------------------------------------------------------------------------
// kernelB: masked softmax + fused gather (att*h + hgc), batched fp16 loads.
// ---------------------------------------------------------------------------
__global__ __launch_bounds__(256) void kernelB(const float* __restrict__ bgc,
                                               float* __restrict__ out) {
    __shared__ int   s_idx[MAXNB];
    __shared__ float s_e[MAXNB];
    __shared__ float s_red[256];

    const int row = blockIdx.x;
    const int tid = threadIdx.x;
    const int cnt = g_ncnt[row];

    float outv;
    if (cnt > 0) {
        const float fsi = g_fs[row];
        float lm = -3e38f;
        for (int k = tid; k < cnt; k += 256) {
            int joff = g_nidx[row * MAXNB + k];      // j*512
            float e = fsi + g_fd[joff >> 9];
            e = (e > 0.f) ? e : 0.2f * e;
            s_idx[k] = joff;
            s_e[k] = e;
            lm = fmaxf(lm, e);
        }
        s_red[tid] = lm;
        __syncthreads();
        #pragma unroll
        for (int o = 128; o; o >>= 1) {
            if (tid < o) s_red[tid] = fmaxf(s_red[tid], s_red[tid + o]);
            __syncthreads();
        }
        const float mx = s_red[0];
        __syncthreads();

        float ls = 0.f;
        for (int k = tid; k < cnt; k += 256) {
            float w = expf(s_e[k] - mx);
            s_e[k] = w;
            ls += w;
        }
        s_red[tid] = ls;
        __syncthreads();
        #pragma unroll
        for (int o = 128; o; o >>= 1) {
            if (tid < o) s_red[tid] += s_red[tid + o];
            __syncthreads();
        }
        const float inv = 1.0f / s_red[0];
        __syncthreads();

        // gather: thread tid owns output column tid; 8-way batched for MLP
        const __half* hp = (const __half*)g_pack;
        float acc_att = 0.f, acc_gc = 0.f;
        int k = 0;
        for (; k + 8 <= cnt; k += 8) {
            __half ha[8], ga[8];
            float wv[8];
            #pragma unroll
            for (int u = 0; u < 8; u++) {
                int joff = s_idx[k + u];
                ha[u] = hp[joff + tid];
                ga[u] = hp[joff + 256 + tid];
                wv[u] = s_e[k + u];
            }
            #pragma unroll
            for (int u = 0; u < 8; u++) {
                acc_att += wv[u] * __half2float(ha[u]);
                acc_gc  += __half2float(ga[u]);
            }
        }
        for (; k < cnt; k++) {
            int joff = s_idx[k];
            acc_att += s_e[k] * __half2float(hp[joff + tid]);
            acc_gc  += __half2float(hp[joff + 256 + tid]);
        }
        outv = bgc[tid] + inv * acc_att + acc_gc;
    } else {
        // all-masked row: softmax uniform 1/N over all cols; gc = bias only
        const __half* hp = (const __half*)g_pack;
        float acc = 0.f;
        for (int j = 0; j < NN; j++)
            acc += __half2float(hp[(size_t)j * 512 + tid]);
        outv = bgc[tid] + acc * (1.0f / (float)NN);
    }
    out[(size_t)row * OUTF + tid] = outv;
}

// ---------------------------------------------------------------------------
extern "C" void kernel_launch(void* const* d_in, const int* in_sizes, int n_in,
                              void* d_out, int out_size) {
    const float* X   = (const float*)d_in[0];  // [8192, 512]
    const float* adj = (const float*)d_in[1];  // [8192, 8192]
    const float* W   = (const float*)d_in[2];  // [512, 256]
    const float* a   = (const float*)d_in[3];  // [512, 1]
    const float* Wgc = (const float*)d_in[4];  // [512, 256]
    const float* bgc = (const float*)d_in[5];  // [256]
    float* out = (float*)d_out;                // [8192, 256]

    prepX<<<NN * INF / 4 / 256, 256>>>(X);
    prepB<<<512, 256>>>(W, Wgc);
    kernelG<<<256 + NN, 256>>>(a, adj);
    kernelR<<<NN / 256, 256>>>();
    kernelB<<<NN, 256>>>(bgc, out);
}

// round 7
// speedup vs baseline: 1.4080x; 1.1354x over previous
#include <cuda_runtime.h>
#include <cuda_fp16.h>
#include <cuda_bf16.h>
#include <cstdint>

#define NN    8192
#define INF   512
#define OUTF  256
#define MAXNB 1024

// ---------------- scratch (__device__ globals: allocation-free rule) --------
__device__ float          g_fsp[4][NN];     // f_src partials (bn*2+wn)
__device__ float          g_fdp[4][NN];
__device__ __half         g_pack[NN * 512]; // [row][0..255]=h, [256..511]=hgc
__device__ int            g_ncnt[NN];
__device__ int            g_nidx[NN * MAXNB]; // pre-scaled j*512
__device__ __nv_bfloat16  g_xh[NN * INF];   // bf16 hi of X  [row][512]
__device__ __nv_bfloat16  g_xl[NN * INF];   // bf16 lo of X
__device__ __nv_bfloat16  g_bh[INF * 512];  // [k][512] = W | Wgc (hi)
__device__ __nv_bfloat16  g_bl[INF * 512];  // lo

// ---------------- helpers ---------------------------------------------------
__device__ __forceinline__ uint32_t smem_u32(const void* p) {
    uint32_t a;
    asm("{ .reg .u64 t; cvta.to.shared.u64 t, %1; cvt.u32.u64 %0, t; }"
        : "=r"(a) : "l"(p));
    return a;
}
#define CPASYNC16(dst, src) \
    asm volatile("cp.async.cg.shared.global [%0], [%1], 16;" \
                 :: "r"(dst), "l"(src) : "memory")
#define CPCOMMIT() asm volatile("cp.async.commit_group;" ::: "memory")
#define CPWAIT(n)  asm volatile("cp.async.wait_group %0;" :: "n"(n) : "memory")

__device__ __forceinline__ void ldsm_x4(uint32_t (&r)[4], uint32_t addr) {
    asm volatile("ldmatrix.sync.aligned.m8n8.x4.shared.b16 {%0,%1,%2,%3}, [%4];"
                 : "=r"(r[0]), "=r"(r[1]), "=r"(r[2]), "=r"(r[3]) : "r"(addr));
}
__device__ __forceinline__ void ldsm_x4t(uint32_t (&r)[4], uint32_t addr) {
    asm volatile("ldmatrix.sync.aligned.m8n8.x4.trans.shared.b16 {%0,%1,%2,%3}, [%4];"
                 : "=r"(r[0]), "=r"(r[1]), "=r"(r[2]), "=r"(r[3]) : "r"(addr));
}
__device__ __forceinline__ void mma_bf16(float* c, const uint32_t* a,
                                         uint32_t b0, uint32_t b1) {
    asm volatile("mma.sync.aligned.m16n8k16.row.col.f32.bf16.bf16.f32 "
                 "{%0,%1,%2,%3}, {%4,%5,%6,%7}, {%8,%9}, {%0,%1,%2,%3};"
                 : "+f"(c[0]), "+f"(c[1]), "+f"(c[2]), "+f"(c[3])
                 : "r"(a[0]), "r"(a[1]), "r"(a[2]), "r"(a[3]), "r"(b0), "r"(b1));
}

// ---------------------------------------------------------------------------
// prepX: X fp32 -> (Xh, Xl) bf16 split
// ---------------------------------------------------------------------------
__global__ __launch_bounds__(256) void prepX(const float* __restrict__ X) {
    int i = blockIdx.x * 256 + threadIdx.x;          // float4 index
    float4 v = ((const float4*)X)[i];
    __nv_bfloat16 hv[4], lv[4];
    float f[4] = {v.x, v.y, v.z, v.w};
    #pragma unroll
    for (int j = 0; j < 4; j++) {
        hv[j] = __float2bfloat16_rn(f[j]);
        lv[j] = __float2bfloat16_rn(f[j] - __bfloat162float(hv[j]));
    }
    *(uint2*)(g_xh + (size_t)i * 4) = *(uint2*)hv;
    *(uint2*)(g_xl + (size_t)i * 4) = *(uint2*)lv;
}

// ---------------------------------------------------------------------------
// prepB: W,Wgc [512][256] fp32 -> g_bh/g_bl [512][512] bf16 (no transpose)
// ---------------------------------------------------------------------------
__global__ __launch_bounds__(256) void prepB(const float* __restrict__ W,
                                             const float* __restrict__ Wgc) {
    int k = blockIdx.x, n = threadIdx.x;
    float w = W[k * 256 + n];
    __nv_bfloat16 hb = __float2bfloat16_rn(w);
    g_bh[k * 512 + n] = hb;
    g_bl[k * 512 + n] = __float2bfloat16_rn(w - __bfloat162float(hb));
    float wg = Wgc[k * 256 + n];
    hb = __float2bfloat16_rn(wg);
    g_bh[k * 512 + 256 + n] = hb;
    g_bl[k * 512 + 256 + n] = __float2bfloat16_rn(wg - __bfloat162float(hb));
}

// ---------------------------------------------------------------------------
// kernelG (heterogeneous): blocks [0,256) HMMA GEMM, blocks [256,256+NN) scan
// __launch_bounds__(256,2): cap regs at 128 so the DRAM-bound scan blocks get
// >=2 CTAs/SM instead of being starved by the GEMM branch's register demand.
// ---------------------------------------------------------------------------
#define ABYTES 10240
#define BUFB   18944
__global__ __launch_bounds__(256, 2) void kernelG(const float* __restrict__ avec,
                                                  const float* __restrict__ adj) {
    __shared__ __align__(16) char sm_ab[2 * BUFB];
    __shared__ float s_avec[512];
    __shared__ int s_cnt;

    const int bid = blockIdx.x;
    const int tid = threadIdx.x;

    if (bid >= 256) {
        // -------- adjacency scan --------
        int row = bid - 256;
        if (tid == 0) s_cnt = 0;
        __syncthreads();
        const float4* arow = (const float4*)(adj + (size_t)row * NN);
        #pragma unroll
        for (int r = 0; r < 8; r++) {
            int q = tid + 256 * r;
            float4 v = arow[q];
            int j0 = q * 4;
            if (v.x > 0.f) { int p = atomicAdd(&s_cnt, 1); if (p < MAXNB) g_nidx[row * MAXNB + p] = (j0 + 0) * 512; }
            if (v.y > 0.f) { int p = atomicAdd(&s_cnt, 1); if (p < MAXNB) g_nidx[row * MAXNB + p] = (j0 + 1) * 512; }
            if (v.z > 0.f) { int p = atomicAdd(&s_cnt, 1); if (p < MAXNB) g_nidx[row * MAXNB + p] = (j0 + 2) * 512; }
            if (v.w > 0.f) { int p = atomicAdd(&s_cnt, 1); if (p < MAXNB) g_nidx[row * MAXNB + p] = (j0 + 3) * 512; }
        }
        __syncthreads();
        if (tid == 0) g_ncnt[row] = min(s_cnt, MAXNB);
        return;
    }

    // -------- GEMM block --------
    const int bm = bid & 63, bn = bid >> 6;          // bn: 0,1=h  2,3=hgc
    const int m0 = bm * 128;
    const int wid = tid >> 5, lane = tid & 31;
    const int wm = wid & 3, wn = wid >> 2;           // warp tile 32m x 64n
    const uint32_t smbase = smem_u32(sm_ab);

    s_avec[tid] = avec[tid];
    s_avec[tid + 256] = avec[tid + 256];

    float cacc[2][8][4];
    #pragma unroll
    for (int i = 0; i < 2; i++)
        #pragma unroll
        for (int j = 0; j < 8; j++)
            #pragma unroll
            for (int e = 0; e < 4; e++) cacc[i][j][e] = 0.f;

    auto issue = [&](int c) {
        uint32_t buf = smbase + (uint32_t)(c & 1) * BUFB;
        int seg = c >> 4;
        const uint4* asrc = (const uint4*)((seg < 2) ? g_xh : g_xl);
        const uint4* bsrc = (const uint4*)((seg == 1) ? g_bl : g_bh);
        int kq = (c & 15) * 4;                       // A uint4 col offset
        #pragma unroll
        for (int i = 0; i < 2; i++) {
            int idx = tid + 256 * i;
            int r = idx >> 2, q = idx & 3;
            CPASYNC16(buf + r * 80 + q * 16, asrc + (size_t)(m0 + r) * 64 + kq + q);
        }
        int kr0 = (c & 15) * 32;                     // B k-row base
        #pragma unroll
        for (int i = 0; i < 2; i++) {
            int idx = tid + 256 * i;
            int rr = idx >> 4, q = idx & 15;
            CPASYNC16(buf + ABYTES + rr * 272 + q * 16,
                      bsrc + (size_t)(kr0 + rr) * 64 + bn * 16 + q);
        }
    };

    issue(0); CPCOMMIT();
    for (int c = 0; c < 48; c++) {
        if (c + 1 < 48) { issue(c + 1); CPCOMMIT(); CPWAIT(1); }
        else            { CPWAIT(0); }
        __syncthreads();
        uint32_t Ab = smbase + (uint32_t)(c & 1) * BUFB;
        uint32_t Bb = Ab + ABYTES;
        #pragma unroll
        for (int ks = 0; ks < 2; ks++) {
            int kk = ks * 16;
            uint32_t a[2][4], b[4][4];
            #pragma unroll
            for (int mf = 0; mf < 2; mf++)
                ldsm_x4(a[mf], Ab + (uint32_t)((wm * 32 + mf * 16 + (lane & 15)) * 80
                                               + (kk + (lane >> 4) * 8) * 2));
            #pragma unroll
            for (int ng = 0; ng < 4; ng++)
                ldsm_x4t(b[ng], Bb + (uint32_t)((kk + (lane & 15)) * 272
                                                + (wn * 64 + ng * 16 + (lane >> 4) * 8) * 2));
            #pragma unroll
            for (int mf = 0; mf < 2; mf++)
                #pragma unroll
                for (int nf = 0; nf < 8; nf++)
                    mma_bf16(cacc[mf][nf], a[mf],
                             b[nf >> 1][(nf & 1) * 2], b[nf >> 1][(nf & 1) * 2 + 1]);
        }
        __syncthreads();
    }

    // -------- epilogue: fp16 pack + f partials --------
    const int pidx = bn * 2 + wn;                    // valid when bn < 2
    #pragma unroll
    for (int mf = 0; mf < 2; mf++) {
        #pragma unroll
        for (int half = 0; half < 2; half++) {
            int row = m0 + wm * 32 + mf * 16 + (lane >> 2) + half * 8;
            int colbase = bn * 128 + wn * 64 + 2 * (lane & 3);
            __half2* dst = (__half2*)g_pack + ((size_t)row * 512 + colbase) / 2;
            float s1 = 0.f, s2 = 0.f;
            #pragma unroll
            for (int nf = 0; nf < 8; nf++) {
                float v0 = cacc[mf][nf][half * 2 + 0];
                float v1 = cacc[mf][nf][half * 2 + 1];
                if (bn < 2) {
                    int cc = bn * 128 + wn * 64 + nf * 8 + 2 * (lane & 3);
                    s1 += v0 * s_avec[cc] + v1 * s_avec[cc + 1];
                    s2 += v0 * s_avec[256 + cc] + v1 * s_avec[256 + cc + 1];
                }
                dst[nf * 4] = __floats2half2_rn(v0, v1);
            }
            if (bn < 2) {
                s1 += __shfl_xor_sync(0xFFFFFFFFu, s1, 1);
                s1 += __shfl_xor_sync(0xFFFFFFFFu, s1, 2);
                s2 += __shfl_xor_sync(0xFFFFFFFFu, s2, 1);
                s2 += __shfl_xor_sync(0xFFFFFFFFu, s2, 2);
                if ((lane & 3) == 0) {
                    g_fsp[pidx][row] = s1;
                    g_fdp[pidx][row] = s2;
                }
            }
        }
    }
}

// ---------------------------------------------------------------------------
// kernelB: masked softmax + fused gather. 4-way neighbor split x 64 col-threads,
// uint2 (4-col) loads for 4x fewer LDG requests. f partials summed inline.
// ---------------------------------------------------------------------------
__global__ __launch_bounds__(256) void kernelB(const float* __restrict__ bgc,
                                               float* __restrict__ out) {
    __shared__ int    s_idx[MAXNB];
    __shared__ float  s_e[MAXNB];
    __shared__ float  s_red[256];
    __shared__ float4 s_att[256];
    __shared__ float4 s_gc[256];

    const int row = blockIdx.x;
    const int tid = threadIdx.x;
    const int cnt = g_ncnt[row];

    if (cnt > 0) {
        const float fsi = g_fsp[0][row] + g_fsp[1][row] +
                          g_fsp[2][row] + g_fsp[3][row];
        float lm = -3e38f;
        for (int k = tid; k < cnt; k += 256) {
            int joff = g_nidx[row * MAXNB + k];      // j*512
            int j = joff >> 9;
            float e = fsi + g_fdp[0][j] + g_fdp[1][j] + g_fdp[2][j] + g_fdp[3][j];
            e = (e > 0.f) ? e : 0.2f * e;
            s_idx[k] = joff;
            s_e[k] = e;
            lm = fmaxf(lm, e);
        }
        s_red[tid] = lm;
        __syncthreads();
        #pragma unroll
        for (int o = 128; o; o >>= 1) {
            if (tid < o) s_red[tid] = fmaxf(s_red[tid], s_red[tid + o]);
            __syncthreads();
        }
        const float mx = s_red[0];
        __syncthreads();

        float ls = 0.f;
        for (int k = tid; k < cnt; k += 256) {
            float w = expf(s_e[k] - mx);
            s_e[k] = w;
            ls += w;
        }
        s_red[tid] = ls;
        __syncthreads();
        #pragma unroll
        for (int o = 128; o; o >>= 1) {
            if (tid < o) s_red[tid] += s_red[tid + o];
            __syncthreads();
        }
        const float inv = 1.0f / s_red[0];
        __syncthreads();

        // gather: qg = neighbor subset (k % 4), tc = 4-col group
        const int qg = tid >> 6, tc = tid & 63;
        float aa0 = 0.f, aa1 = 0.f, aa2 = 0.f, aa3 = 0.f;
        float gg0 = 0.f, gg1 = 0.f, gg2 = 0.f, gg3 = 0.f;
        const __half* hp = (const __half*)g_pack;
        #pragma unroll 4
        for (int k = qg; k < cnt; k += 4) {
            int joff = s_idx[k];
            float w = s_e[k];
            uint2 hv = *(const uint2*)(hp + joff + 4 * tc);
            uint2 gv = *(const uint2*)(hp + joff + 256 + 4 * tc);
            float2 h01 = __half22float2(*(const __half2*)&hv.x);
            float2 h23 = __half22float2(*(const __half2*)&hv.y);
            float2 g01 = __half22float2(*(const __half2*)&gv.x);
            float2 g23 = __half22float2(*(const __half2*)&gv.y);
            aa0 += w * h01.x; aa1 += w * h01.y;
            aa2 += w * h23.x; aa3 += w * h23.y;
            gg0 += g01.x; gg1 += g01.y; gg2 += g23.x; gg3 += g23.y;
        }
        s_att[tid] = make_float4(aa0, aa1, aa2, aa3);
        s_gc[tid]  = make_float4(gg0, gg1, gg2, gg3);
        __syncthreads();

        if (tid < 64) {
            float4 a0 = s_att[tid],       a1 = s_att[64 + tid],
                   a2 = s_att[128 + tid], a3 = s_att[192 + tid];
            float4 g0 = s_gc[tid],        g1 = s_gc[64 + tid],
                   g2 = s_gc[128 + tid],  g3 = s_gc[192 + tid];
            float4 b = *(const float4*)(bgc + 4 * tid);
            float4 o;
            o.x = b.x + inv * (a0.x + a1.x + a2.x + a3.x) + (g0.x + g1.x + g2.x + g3.x);
            o.y = b.y + inv * (a0.y + a1.y + a2.y + a3.y) + (g0.y + g1.y + g2.y + g3.y);
            o.z = b.z + inv * (a0.z + a1.z + a2.z + a3.z) + (g0.z + g1.z + g2.z + g3.z);
            o.w = b.w + inv * (a0.w + a1.w + a2.w + a3.w) + (g0.w + g1.w + g2.w + g3.w);
            *(float4*)(out + (size_t)row * OUTF + 4 * tid) = o;
        }
    } else {
        // all-masked row: softmax uniform 1/N over all cols; gc = bias only
        const __half* hp = (const __half*)g_pack;
        float acc = 0.f;
        for (int j = 0; j < NN; j++)
            acc += __half2float(hp[(size_t)j * 512 + tid]);
        out[(size_t)row * OUTF + tid] = bgc[tid] + acc * (1.0f / (float)NN);
    }
}

// ---------------------------------------------------------------------------
extern "C" void kernel_launch(void* const* d_in, const int* in_sizes, int n_in,
                              void* d_out, int out_size) {
    const float* X   = (const float*)d_in[0];  // [8192, 512]
    const float* adj = (const float*)d_in[1];  // [8192, 8192]
    const float* W   = (const float*)d_in[2];  // [512, 256]
    const float* a   = (const float*)d_in[3];  // [512, 1]
    const float* Wgc = (const float*)d_in[4];  // [512, 256]
    const float* bgc = (const float*)d_in[5];  // [256]
    float* out = (float*)d_out;                // [8192, 256]

    prepX<<<NN * INF / 4 / 256, 256>>>(X);
    prepB<<<512, 256>>>(W, Wgc);
    kernelG<<<256 + NN, 256>>>(a, adj);
    kernelB<<<NN, 256>>>(bgc, out);
}